// round 2
// baseline (speedup 1.0000x reference)
#include <cuda_runtime.h>
#include <cstdint>

// Shapes (fixed by the problem)
#define B_    64
#define S_    16
#define J_    256
#define QDIM_ 512
#define IDIM_ 512
#define HDIM_ 256
#define BS_   (B_ * S_)   // 1024

// Scratch (allocation-free rule: __device__ globals)
__device__ float g_qt[B_ * IDIM_];         // q-tilde per batch: scale * Wk^T (Wq q)  [64, 512]
__device__ float g_pooled[BS_ * IDIM_];    // weighted-pooled inputs                  [1024, 512]
__device__ int   g_mask_u8;                // 1 = mask is 1-byte bool, 0 = int32

// ---------------------------------------------------------------------------
// Kernel 0: detect mask dtype. If the mask buffer holds int32 {0,1}, every
// 32-bit word is <= 1. If it holds 1-byte bools, some word among the first
// 1024 has a byte set above bit 0 (prob of miss ~ 16^-1024 for random mask).
// Deterministic (pure function of the input buffer).
// ---------------------------------------------------------------------------
__global__ void detect_mask_kernel(const unsigned* __restrict__ mask_words)
{
    __shared__ int any_gt1;
    if (threadIdx.x == 0) any_gt1 = 0;
    __syncthreads();
    int local = 0;
    for (int i = threadIdx.x; i < 1024; i += blockDim.x)
        if (mask_words[i] > 1u) local = 1;
    if (local) any_gt1 = 1;   // benign race: only ever writes 1
    __syncthreads();
    if (threadIdx.x == 0) g_mask_u8 = any_gt1;
}

// ---------------------------------------------------------------------------
// Kernel 1: q̃_b = scale * (Wk^T (Wq query_b))
// grid = 64 blocks (one per batch), 256 threads
// ---------------------------------------------------------------------------
__global__ __launch_bounds__(256) void qt_kernel(
    const float* __restrict__ query,  // [64, 512]
    const float* __restrict__ Wq,     // [256, 512]
    const float* __restrict__ Wk)     // [256, 512]
{
    const int b   = blockIdx.x;
    const int tid = threadIdx.x;

    __shared__ float sq[QDIM_];   // query row
    __shared__ float sQ[HDIM_];   // projected Q row

    sq[tid]        = query[b * QDIM_ + tid];
    sq[tid + 256]  = query[b * QDIM_ + tid + 256];
    __syncthreads();

    // Q[b,h] = sum_q query[b,q] * Wq[h,q]   (thread = h)
    {
        const float4* wq = reinterpret_cast<const float4*>(Wq + (size_t)tid * QDIM_);
        const float4* q4 = reinterpret_cast<const float4*>(sq);
        float acc = 0.f;
        #pragma unroll 8
        for (int k = 0; k < QDIM_ / 4; ++k) {
            float4 w = wq[k], q = q4[k];
            acc = fmaf(w.x, q.x, acc);
            acc = fmaf(w.y, q.y, acc);
            acc = fmaf(w.z, q.z, acc);
            acc = fmaf(w.w, q.w, acc);
        }
        sQ[tid] = acc;
    }
    __syncthreads();

    // qt[b,i] = scale * sum_h Q[b,h] * Wk[h,i]   (coalesced over i)
    const float scale = 0.0625f;  // 1/sqrt(HDIM=256)
    for (int i = tid; i < IDIM_; i += 256) {
        float acc = 0.f;
        #pragma unroll 4
        for (int h = 0; h < HDIM_; ++h)
            acc = fmaf(sQ[h], Wk[(size_t)h * IDIM_ + i], acc);
        g_qt[b * IDIM_ + i] = acc * scale;
    }
}

// ---------------------------------------------------------------------------
// Kernel 2: flash-style masked softmax-pooling over J (single pass over X)
// grid = 1024 blocks (one per (b,s)), 256 threads = 8 warps.
// Each warp owns rows j = wid, wid+8, ... and keeps running (m, d, p[512]).
// ---------------------------------------------------------------------------
__global__ __launch_bounds__(256) void flash_pool_kernel(
    const float* __restrict__ X,     // [64,16,256,512]
    const void*  __restrict__ mask)  // [64,16,256]  bool-u8 OR int32 (runtime-detected)
{
    const int bs   = blockIdx.x;
    const int b    = bs >> 4;
    const int tid  = threadIdx.x;
    const int wid  = tid >> 5;
    const int lane = tid & 31;

    const float* x = X + (size_t)bs * J_ * IDIM_;
    const int mask_is_u8 = g_mask_u8;
    const uint8_t* mk8 = (const uint8_t*)mask + (size_t)bs * J_;
    const int*     mk32 = (const int*)mask + (size_t)bs * J_;

    __shared__ float s_qt[IDIM_];          // 2 KB
    __shared__ float s_p[8][IDIM_];        // 16 KB per-warp pooled partials
    __shared__ float s_m[8], s_d[8];

    s_qt[tid]       = g_qt[b * IDIM_ + tid];
    s_qt[tid + 256] = g_qt[b * IDIM_ + tid + 256];
    __syncthreads();

    // Lane-resident q̃ slice as float4: col-group lane + 32*k, k=0..3
    float4 qv[4];
    {
        const float4* q4 = reinterpret_cast<const float4*>(s_qt);
        #pragma unroll
        for (int k = 0; k < 4; ++k) qv[k] = q4[lane + 32 * k];
    }

    float4 p[4];
    #pragma unroll
    for (int k = 0; k < 4; ++k) p[k] = make_float4(0.f, 0.f, 0.f, 0.f);
    float m = -1e30f, d = 0.f;

    for (int j = wid; j < J_; j += 8) {
        const float4* xr = reinterpret_cast<const float4*>(x + (size_t)j * IDIM_);
        float4 xv[4];
        #pragma unroll
        for (int k = 0; k < 4; ++k) xv[k] = xr[lane + 32 * k];

        // score = q̃ · x_j  (partial dot, then warp tree-reduce)
        float s = 0.f;
        #pragma unroll
        for (int k = 0; k < 4; ++k) {
            s = fmaf(xv[k].x, qv[k].x, s);
            s = fmaf(xv[k].y, qv[k].y, s);
            s = fmaf(xv[k].z, qv[k].z, s);
            s = fmaf(xv[k].w, qv[k].w, s);
        }
        #pragma unroll
        for (int off = 16; off > 0; off >>= 1)
            s += __shfl_xor_sync(0xffffffffu, s, off);

        const bool masked = mask_is_u8 ? (mk8[j] != 0) : (mk32[j] != 0);
        if (masked) s = -1e30f;   // effectively -inf; finite keeps exp math NaN-free

        const float mn = fmaxf(m, s);
        const float f  = __expf(m - mn);   // rescale of running state
        const float w  = __expf(s - mn);   // weight of this row
        m = mn;
        d = fmaf(d, f, w);
        #pragma unroll
        for (int k = 0; k < 4; ++k) {
            p[k].x = fmaf(p[k].x, f, w * xv[k].x);
            p[k].y = fmaf(p[k].y, f, w * xv[k].y);
            p[k].z = fmaf(p[k].z, f, w * xv[k].z);
            p[k].w = fmaf(p[k].w, f, w * xv[k].w);
        }
    }

    // Stash per-warp state
    if (lane == 0) { s_m[wid] = m; s_d[wid] = d; }
    {
        float4* pw = reinterpret_cast<float4*>(&s_p[wid][0]);
        #pragma unroll
        for (int k = 0; k < 4; ++k) pw[lane + 32 * k] = p[k];
    }
    __syncthreads();

    // Cross-warp merge (every thread computes coefs redundantly; 8 exps each)
    float M = -1e30f;
    #pragma unroll
    for (int w = 0; w < 8; ++w) M = fmaxf(M, s_m[w]);
    float coef[8];
    float D = 0.f;
    #pragma unroll
    for (int w = 0; w < 8; ++w) {
        coef[w] = __expf(s_m[w] - M);
        D = fmaf(s_d[w], coef[w], D);
    }
    const float inv = 1.f / D;

    for (int i = tid; i < IDIM_; i += 256) {
        float acc = 0.f;
        #pragma unroll
        for (int w = 0; w < 8; ++w) acc = fmaf(s_p[w][i], coef[w], acc);
        g_pooled[(size_t)bs * IDIM_ + i] = acc * inv;
    }
}

// ---------------------------------------------------------------------------
// Kernel 3: out[m, h] = sum_i pooled[m, i] * Wv[h, i]
// grid = 128 blocks (8 m-rows each), 256 threads (thread = h).
// ---------------------------------------------------------------------------
#define MT_ 8
__global__ __launch_bounds__(256) void epilogue_kernel(
    const float* __restrict__ Wv,   // [256, 512]
    float* __restrict__ out)        // [1024, 256]
{
    const int m0  = blockIdx.x * MT_;
    const int tid = threadIdx.x;

    __shared__ float sP[MT_][IDIM_];   // 16 KB
    for (int idx = tid; idx < MT_ * IDIM_; idx += 256)
        sP[idx >> 9][idx & 511] = g_pooled[(size_t)(m0 + (idx >> 9)) * IDIM_ + (idx & 511)];
    __syncthreads();

    const int h = tid;
    const float4* wr = reinterpret_cast<const float4*>(Wv + (size_t)h * IDIM_);
    float acc[MT_];
    #pragma unroll
    for (int mm = 0; mm < MT_; ++mm) acc[mm] = 0.f;

    #pragma unroll 4
    for (int i4 = 0; i4 < IDIM_ / 4; ++i4) {
        const float4 w4 = wr[i4];
        const int i = i4 * 4;
        #pragma unroll
        for (int mm = 0; mm < MT_; ++mm) {
            acc[mm] = fmaf(w4.x, sP[mm][i + 0], acc[mm]);
            acc[mm] = fmaf(w4.y, sP[mm][i + 1], acc[mm]);
            acc[mm] = fmaf(w4.z, sP[mm][i + 2], acc[mm]);
            acc[mm] = fmaf(w4.w, sP[mm][i + 3], acc[mm]);
        }
    }
    #pragma unroll
    for (int mm = 0; mm < MT_; ++mm)
        out[(size_t)(m0 + mm) * HDIM_ + h] = acc[mm];
}

// ---------------------------------------------------------------------------
// Launch
// Inputs (metadata order): query, other_semesters, mask, Wq, Wk, Wv
// ---------------------------------------------------------------------------
extern "C" void kernel_launch(void* const* d_in, const int* in_sizes, int n_in,
                              void* d_out, int out_size)
{
    const float* query = (const float*)d_in[0];
    const float* X     = (const float*)d_in[1];
    const void*  mask  = d_in[2];
    const float* Wq    = (const float*)d_in[3];
    const float* Wk    = (const float*)d_in[4];
    const float* Wv    = (const float*)d_in[5];
    float*       out   = (float*)d_out;

    detect_mask_kernel<<<1, 256>>>((const unsigned*)mask);
    qt_kernel<<<B_, 256>>>(query, Wq, Wk);
    flash_pool_kernel<<<BS_, 256>>>(X, mask);
    epilogue_kernel<<<BS_ / MT_, 256>>>(Wv, out);
}